// round 1
// baseline (speedup 1.0000x reference)
#include <cuda_runtime.h>

#define N_ATOMS   50000
#define NUM_ELEM  10
#define LMAX      3
#define SH_DIM    16
#define CIN       128
#define COUT      128
#define TILE_M    64
#define NSEG      (NUM_ELEM * (LMAX + 1))
// max tiles: sum_{e,l} ceil(cnt_e*(2l+1)/64) <= N*16/64 + 40 = 12540
#define GRID_GEMM 12560

__device__ int g_counts[NUM_ELEM];
__device__ int g_cursor[NUM_ELEM];
__device__ int g_offsets[NUM_ELEM];
__device__ int g_species[N_ATOMS];
__device__ int g_order[N_ATOMS];
__device__ int g_tile_prefix[NSEG + 1];

// ---------------- prep kernels ----------------

__global__ void k_init() {
    int t = threadIdx.x;
    if (t < NUM_ELEM) { g_counts[t] = 0; g_cursor[t] = 0; }
}

__global__ void k_hist(const float* __restrict__ y) {
    int n = blockIdx.x * blockDim.x + threadIdx.x;
    if (n >= N_ATOMS) return;
    const float* yr = y + (long)n * NUM_ELEM;
    int s = 0;
    float best = yr[0];
#pragma unroll
    for (int e = 1; e < NUM_ELEM; e++) {
        float v = yr[e];
        if (v > best) { best = v; s = e; }
    }
    g_species[n] = s;
    atomicAdd(&g_counts[s], 1);
}

__global__ void k_scan() {
    // single thread: 10 offsets + 40 tile-prefix entries
    int off = 0;
    for (int e = 0; e < NUM_ELEM; e++) { g_offsets[e] = off; off += g_counts[e]; }
    int tp = 0;
    g_tile_prefix[0] = 0;
    int seg = 0;
    for (int e = 0; e < NUM_ELEM; e++) {
        for (int l = 0; l <= LMAX; l++) {
            int rows = g_counts[e] * (2 * l + 1);
            tp += (rows + TILE_M - 1) / TILE_M;
            g_tile_prefix[++seg] = tp;
        }
    }
}

__global__ void k_scatter() {
    int n = blockIdx.x * blockDim.x + threadIdx.x;
    if (n >= N_ATOMS) return;
    int s = g_species[n];
    int pos = g_offsets[s] + atomicAdd(&g_cursor[s], 1);
    g_order[pos] = n;
}

// ---------------- tile GEMM ----------------
// One CTA: 64 gathered rows (same species e, same l) x W[e,l] (128x128).
// 128 threads, 8x16 thread grid, 8x8 register micro-tile each.

#define SMEM_FLOATS (CIN * COUT + TILE_M * CIN)
#define SMEM_BYTES  (SMEM_FLOATS * 4 + TILE_M * 4)

__global__ __launch_bounds__(128, 2)
void k_gemm(const float* __restrict__ x, const float* __restrict__ w,
            float* __restrict__ out) {
    extern __shared__ float smem[];
    float* Bs = smem;                 // [CIN][COUT] = W[e,l], k-major rows
    float* As = smem + CIN * COUT;    // [TILE_M][CIN]
    int* rowbase = (int*)(As + TILE_M * CIN);

    int t = blockIdx.x;
    int ntiles = g_tile_prefix[NSEG];
    if (t >= ntiles) return;

    // locate segment (<=40 cached reads)
    int seg = 0;
    while (g_tile_prefix[seg + 1] <= t) seg++;
    int e = seg >> 2;
    int l = seg & 3;
    int row0 = (t - g_tile_prefix[seg]) * TILE_M;
    int R = 2 * l + 1;
    int Mseg = g_counts[e] * R;
    int offe = g_offsets[e];
    int tid = threadIdx.x;

    // per-row metadata
    if (tid < TILE_M) {
        int r = row0 + tid;
        int rb = -1;
        if (r < Mseg) {
            int atom = g_order[offe + r / R];
            int sh = l * l + r % R;
            rb = (atom * SH_DIM + sh) * CIN;
        }
        rowbase[tid] = rb;
    }

    // load W[e,l] into SMEM (fully coalesced float4)
    {
        const float4* w4 = (const float4*)(w + ((long)(e * (LMAX + 1) + l)) * CIN * COUT);
        float4* b4 = (float4*)Bs;
#pragma unroll
        for (int i = 0; i < 32; i++) b4[tid + i * 128] = w4[tid + i * 128];
    }
    __syncthreads();

    // gather 64 x-rows into SMEM (2 threads per row, float4)
    {
        int m = tid >> 1;
        int half = tid & 1;
        int rb = rowbase[m];
        if (rb >= 0) {
            const float4* xr = (const float4*)(x + rb) + half * 16;
            float4* ar = (float4*)(As + m * CIN + half * 64);
#pragma unroll
            for (int i = 0; i < 16; i++) ar[i] = xr[i];
        }
    }
    __syncthreads();

    int tcol = tid & 15;   // 16 col-blocks of 8
    int trow = tid >> 4;   // 8 row-blocks of 8

    float acc[8][8];
#pragma unroll
    for (int i = 0; i < 8; i++)
#pragma unroll
        for (int j = 0; j < 8; j++) acc[i][j] = 0.f;

    const float* As_base = As + trow * 8 * CIN;
    const float* Bs_base = Bs + tcol * 8;

#pragma unroll 2
    for (int k4 = 0; k4 < CIN / 4; k4++) {
        float4 a4[8];
#pragma unroll
        for (int i = 0; i < 8; i++)
            a4[i] = *(const float4*)(As_base + i * CIN + k4 * 4);
#pragma unroll
        for (int kk = 0; kk < 4; kk++) {
            int k = k4 * 4 + kk;
            float4 b0 = *(const float4*)(Bs_base + k * COUT);
            float4 b1 = *(const float4*)(Bs_base + k * COUT + 4);
            float b[8] = {b0.x, b0.y, b0.z, b0.w, b1.x, b1.y, b1.z, b1.w};
            float a[8] = {
                kk == 0 ? a4[0].x : kk == 1 ? a4[0].y : kk == 2 ? a4[0].z : a4[0].w,
                kk == 0 ? a4[1].x : kk == 1 ? a4[1].y : kk == 2 ? a4[1].z : a4[1].w,
                kk == 0 ? a4[2].x : kk == 1 ? a4[2].y : kk == 2 ? a4[2].z : a4[2].w,
                kk == 0 ? a4[3].x : kk == 1 ? a4[3].y : kk == 2 ? a4[3].z : a4[3].w,
                kk == 0 ? a4[4].x : kk == 1 ? a4[4].y : kk == 2 ? a4[4].z : a4[4].w,
                kk == 0 ? a4[5].x : kk == 1 ? a4[5].y : kk == 2 ? a4[5].z : a4[5].w,
                kk == 0 ? a4[6].x : kk == 1 ? a4[6].y : kk == 2 ? a4[6].z : a4[6].w,
                kk == 0 ? a4[7].x : kk == 1 ? a4[7].y : kk == 2 ? a4[7].z : a4[7].w};
#pragma unroll
            for (int i = 0; i < 8; i++)
#pragma unroll
                for (int j = 0; j < 8; j++)
                    acc[i][j] += a[i] * b[j];
        }
    }

    const float scale = 0.08838834764831845f;  // 1/sqrt(128)
#pragma unroll
    for (int i = 0; i < 8; i++) {
        int rb = rowbase[trow * 8 + i];
        if (rb < 0) continue;
        float* orow = out + rb + tcol * 8;
        float4 v0 = make_float4(acc[i][0] * scale, acc[i][1] * scale,
                                acc[i][2] * scale, acc[i][3] * scale);
        float4 v1 = make_float4(acc[i][4] * scale, acc[i][5] * scale,
                                acc[i][6] * scale, acc[i][7] * scale);
        *(float4*)orow = v0;
        *((float4*)orow + 1) = v1;
    }
}

// ---------------- launch ----------------

extern "C" void kernel_launch(void* const* d_in, const int* in_sizes, int n_in,
                              void* d_out, int out_size) {
    const float* x = (const float*)d_in[0];        // [N, 16, 128]
    const float* y = (const float*)d_in[1];        // [N, 10]
    const float* w = (const float*)d_in[2];        // [10, 4, 128, 128]
    float* out = (float*)d_out;                    // [N, 16, 128]

    cudaFuncSetAttribute(k_gemm, cudaFuncAttributeMaxDynamicSharedMemorySize,
                         SMEM_BYTES);

    k_init<<<1, 32>>>();
    k_hist<<<(N_ATOMS + 255) / 256, 256>>>(y);
    k_scan<<<1, 1>>>();
    k_scatter<<<(N_ATOMS + 255) / 256, 256>>>();
    k_gemm<<<GRID_GEMM, 128, SMEM_BYTES>>>(x, w, out);
}

// round 2
// speedup vs baseline: 1.7681x; 1.7681x over previous
#include <cuda_runtime.h>
#include <cuda_bf16.h>

#define N_ATOMS   50000
#define NUM_ELEM  10
#define LMAX      3
#define SH_DIM    16
#define CIN       128
#define COUT      128
#define TILE_M    128
#define NSEG      (NUM_ELEM * (LMAX + 1))
// max tiles: sum_{e,l} ceil(cnt_e*(2l+1)/128) <= N*16/128 + 40 = 6290
#define GRID_GEMM 6290
#define AS_STRIDE 132

__device__ int   g_counts[NUM_ELEM];
__device__ int   g_cursor[NUM_ELEM];
__device__ int   g_offsets[NUM_ELEM];
__device__ int   g_species[N_ATOMS];
__device__ int   g_order[N_ATOMS];
__device__ int   g_tile_prefix[NSEG + 1];
// W packed into per-thread mma fragment layout: [seg][ks][nt][lane] -> {hi_b0, hi_b1, lo_b0, lo_b1}
__device__ uint4 g_wpack[NSEG * 4096];

// ---------------- helpers ----------------

__device__ __forceinline__ void split2(float a, float b, unsigned& hi, unsigned& lo) {
    __nv_bfloat16 ha = __float2bfloat16(a);
    __nv_bfloat16 hb = __float2bfloat16(b);
    float ra = a - __bfloat162float(ha);
    float rb = b - __bfloat162float(hb);
    __nv_bfloat162 hp; hp.x = ha; hp.y = hb;
    __nv_bfloat162 lp; lp.x = __float2bfloat16(ra); lp.y = __float2bfloat16(rb);
    hi = *(unsigned*)&hp;
    lo = *(unsigned*)&lp;
}

__device__ __forceinline__ void mma_bf16(float* c, const unsigned* a, unsigned b0, unsigned b1) {
    asm volatile(
        "mma.sync.aligned.m16n8k16.row.col.f32.bf16.bf16.f32 "
        "{%0,%1,%2,%3}, {%4,%5,%6,%7}, {%8,%9}, {%0,%1,%2,%3};\n"
        : "+f"(c[0]), "+f"(c[1]), "+f"(c[2]), "+f"(c[3])
        : "r"(a[0]), "r"(a[1]), "r"(a[2]), "r"(a[3]), "r"(b0), "r"(b1));
}

// ---------------- prep kernels ----------------

__global__ void k_init() {
    int t = threadIdx.x;
    if (t < NUM_ELEM) { g_counts[t] = 0; g_cursor[t] = 0; }
}

__global__ void k_hist(const float* __restrict__ y) {
    __shared__ int cnt[NUM_ELEM];
    int tid = threadIdx.x;
    if (tid < NUM_ELEM) cnt[tid] = 0;
    __syncthreads();
    int n = blockIdx.x * blockDim.x + tid;
    int s = -1;
    if (n < N_ATOMS) {
        const float* yr = y + (long)n * NUM_ELEM;
        float best = yr[0]; s = 0;
#pragma unroll
        for (int e = 1; e < NUM_ELEM; e++) {
            float v = yr[e];
            if (v > best) { best = v; s = e; }
        }
        g_species[n] = s;
        atomicAdd(&cnt[s], 1);
    }
    __syncthreads();
    if (tid < NUM_ELEM && cnt[tid] > 0) atomicAdd(&g_counts[tid], cnt[tid]);
}

__global__ void k_scan() {
    int off = 0;
    for (int e = 0; e < NUM_ELEM; e++) { g_offsets[e] = off; off += g_counts[e]; }
    int tp = 0;
    g_tile_prefix[0] = 0;
    int seg = 0;
    for (int e = 0; e < NUM_ELEM; e++)
        for (int l = 0; l <= LMAX; l++) {
            int rows = g_counts[e] * (2 * l + 1);
            tp += (rows + TILE_M - 1) / TILE_M;
            g_tile_prefix[++seg] = tp;
        }
}

__global__ void k_scatter() {
    __shared__ int cnt[NUM_ELEM];
    __shared__ int base[NUM_ELEM];
    int tid = threadIdx.x;
    if (tid < NUM_ELEM) cnt[tid] = 0;
    __syncthreads();
    int n = blockIdx.x * blockDim.x + tid;
    int s = -1, myrank = 0;
    if (n < N_ATOMS) {
        s = g_species[n];
        myrank = atomicAdd(&cnt[s], 1);
    }
    __syncthreads();
    if (tid < NUM_ELEM) base[tid] = cnt[tid] ? atomicAdd(&g_cursor[tid], cnt[tid]) : 0;
    __syncthreads();
    if (n < N_ATOMS) g_order[g_offsets[s] + base[s] + myrank] = n;
}

// Pack W[e][l] into mma B-fragment layout, bf16 hi/lo split.
// slot idx -> seg, ks (k-step), nt (8-col tile), lane. Thread 'lane' of the mma
// needs B[k0..k0+1][n] (b0) and B[k0+8..k0+9][n] (b1) with k0=16*ks+2*(lane&3),
// n=8*nt+(lane>>2).
__global__ void k_wpack(const float* __restrict__ w) {
    int idx = blockIdx.x * blockDim.x + threadIdx.x;
    if (idx >= NSEG * 4096) return;
    int seg = idx >> 12;
    int rem = idx & 4095;
    int ks = rem >> 9;
    int nt = (rem >> 5) & 15;
    int t  = rem & 31;
    int k0 = ks * 16 + 2 * (t & 3);
    int n  = nt * 8 + (t >> 2);
    const float* W = w + (long)seg * CIN * COUT;
    float v0 = W[(k0    ) * COUT + n];
    float v1 = W[(k0 + 1) * COUT + n];
    float v2 = W[(k0 + 8) * COUT + n];
    float v3 = W[(k0 + 9) * COUT + n];
    unsigned h0, l0, h1, l1;
    split2(v0, v1, h0, l0);
    split2(v2, v3, h1, l1);
    g_wpack[idx] = make_uint4(h0, h1, l0, l1);
}

// ---------------- tensor-core tile GEMM ----------------
// CTA: 128 gathered rows (same species, same l) x W[e,l] 128x128.
// 256 threads / 8 warps. Warp w: rows [(w>>1)*32, +32), col-half (w&1)*64.
// bf16 split (hi+lo), 3 mma passes -> fp32-like accuracy.

#define SMEM_BYTES (TILE_M * AS_STRIDE * 4 + 4096 * 16 + TILE_M * 4)

__global__ __launch_bounds__(256, 1)
void k_gemm(const float* __restrict__ x, float* __restrict__ out) {
    extern __shared__ char smem_raw[];
    float* As      = (float*)smem_raw;                              // [128][AS_STRIDE] fp32
    uint4* Bs      = (uint4*)(smem_raw + TILE_M * AS_STRIDE * 4);   // 4096 packed frags
    int*   rowbase = (int*)(Bs + 4096);

    int t = blockIdx.x;
    if (t >= g_tile_prefix[NSEG]) return;
    int seg = 0;
    while (g_tile_prefix[seg + 1] <= t) seg++;
    int e = seg >> 2, l = seg & 3;
    int row0 = (t - g_tile_prefix[seg]) * TILE_M;
    int R = 2 * l + 1;
    int Mseg = g_counts[e] * R;
    int offe = g_offsets[e];
    int tid = threadIdx.x;

    // per-row x base offsets
    if (tid < TILE_M) {
        int r = row0 + tid;
        int rb = -1;
        if (r < Mseg) {
            int atom = g_order[offe + r / R];
            rb = (atom * SH_DIM + l * l + r % R) * CIN;
        }
        rowbase[tid] = rb;
    }

    // copy pre-packed W frags (LDG.128 -> STS.128, conflict-free)
    {
        const uint4* wp = g_wpack + seg * 4096;
#pragma unroll
        for (int i = 0; i < 16; i++) Bs[tid + i * 256] = wp[tid + i * 256];
    }
    __syncthreads();

    // gather 128 x-rows (2 threads/row, float4)
    {
        int m = tid >> 1, half = tid & 1;
        int rb = rowbase[m];
        float4* dst = (float4*)(As + m * AS_STRIDE) + half * 16;
        if (rb >= 0) {
            const float4* src = (const float4*)(x + rb) + half * 16;
#pragma unroll
            for (int i = 0; i < 16; i++) dst[i] = src[i];
        } else {
            float4 z = make_float4(0.f, 0.f, 0.f, 0.f);
#pragma unroll
            for (int i = 0; i < 16; i++) dst[i] = z;
        }
    }
    __syncthreads();

    int w    = tid >> 5;
    int lane = tid & 31;
    int g    = lane >> 2;
    int tig  = lane & 3;
    int mrow0 = (w >> 1) * 32;      // 32 rows per warp (2 m-tiles)
    int nh    = (w & 1) * 8;        // 8 n-tiles per warp (64 cols)

    float acc[2][8][4];
#pragma unroll
    for (int m = 0; m < 2; m++)
#pragma unroll
        for (int nt = 0; nt < 8; nt++)
#pragma unroll
            for (int i = 0; i < 4; i++) acc[m][nt][i] = 0.f;

#pragma unroll
    for (int ks = 0; ks < 8; ks++) {
        unsigned ah[2][4], al[2][4];
#pragma unroll
        for (int m = 0; m < 2; m++) {
            const float* Ab = As + (mrow0 + m * 16) * AS_STRIDE + ks * 16;
            float2 p0 = *(const float2*)(Ab + (g    ) * AS_STRIDE + 2 * tig    );
            float2 p1 = *(const float2*)(Ab + (g + 8) * AS_STRIDE + 2 * tig    );
            float2 p2 = *(const float2*)(Ab + (g    ) * AS_STRIDE + 2 * tig + 8);
            float2 p3 = *(const float2*)(Ab + (g + 8) * AS_STRIDE + 2 * tig + 8);
            split2(p0.x, p0.y, ah[m][0], al[m][0]);
            split2(p1.x, p1.y, ah[m][1], al[m][1]);
            split2(p2.x, p2.y, ah[m][2], al[m][2]);
            split2(p3.x, p3.y, ah[m][3], al[m][3]);
        }
#pragma unroll
        for (int ntl = 0; ntl < 8; ntl++) {
            uint4 B = Bs[(ks * 16 + nh + ntl) * 32 + lane];  // one LDS.128 = 4 frag regs
#pragma unroll
            for (int m = 0; m < 2; m++) {
                mma_bf16(acc[m][ntl], ah[m], B.x, B.y);  // Ah * Wh
                mma_bf16(acc[m][ntl], ah[m], B.z, B.w);  // Ah * Wl
                mma_bf16(acc[m][ntl], al[m], B.x, B.y);  // Al * Wh
            }
        }
    }

    const float scale = 0.08838834764831845f;  // 1/sqrt(128)
#pragma unroll
    for (int m = 0; m < 2; m++) {
        int rlo = rowbase[mrow0 + m * 16 + g];
        int rhi = rowbase[mrow0 + m * 16 + g + 8];
#pragma unroll
        for (int ntl = 0; ntl < 8; ntl++) {
            int col = (nh + ntl) * 8 + 2 * tig;
            if (rlo >= 0)
                *(float2*)(out + rlo + col) =
                    make_float2(acc[m][ntl][0] * scale, acc[m][ntl][1] * scale);
            if (rhi >= 0)
                *(float2*)(out + rhi + col) =
                    make_float2(acc[m][ntl][2] * scale, acc[m][ntl][3] * scale);
        }
    }
}

// ---------------- launch ----------------

extern "C" void kernel_launch(void* const* d_in, const int* in_sizes, int n_in,
                              void* d_out, int out_size) {
    const float* x = (const float*)d_in[0];   // [N, 16, 128]
    const float* y = (const float*)d_in[1];   // [N, 10]
    const float* w = (const float*)d_in[2];   // [10, 4, 128, 128]
    float* out = (float*)d_out;               // [N, 16, 128]

    cudaFuncSetAttribute(k_gemm, cudaFuncAttributeMaxDynamicSharedMemorySize,
                         SMEM_BYTES);

    k_init<<<1, 32>>>();
    k_hist<<<(N_ATOMS + 255) / 256, 256>>>(y);
    k_scan<<<1, 1>>>();
    k_scatter<<<(N_ATOMS + 255) / 256, 256>>>();
    k_wpack<<<(NSEG * 4096 + 255) / 256, 256>>>(w);
    k_gemm<<<GRID_GEMM, 256, SMEM_BYTES>>>(x, out);
}